// round 3
// baseline (speedup 1.0000x reference)
#include <cuda_runtime.h>
#include <math.h>

#define N_ANT 64
#define HID   128
#define AP    132   // activation pitch (floats): 16B-aligned rows
#define WP    132   // staged-weight pitch
#define WCH   (32 * WP)
#define SP    65    // score pitch
#define NTH   512

typedef unsigned long long u64;

__device__ __forceinline__ u64 pack2(float lo, float hi) {
    u64 r; asm("mov.b64 %0,{%1,%2};" : "=l"(r) : "f"(lo), "f"(hi)); return r;
}
__device__ __forceinline__ u64 dup2(float v) { return pack2(v, v); }
__device__ __forceinline__ u64 ffma2(u64 a, u64 b, u64 c) {
    u64 d; asm("fma.rn.f32x2 %0,%1,%2,%3;" : "=l"(d) : "l"(a), "l"(b), "l"(c)); return d;
}
__device__ __forceinline__ float2 unpack2(u64 p) {
    float2 f; asm("mov.b64 {%0,%1},%2;" : "=f"(f.x), "=f"(f.y) : "l"(p)); return f;
}
__device__ __forceinline__ float f4c(const float4& v, int c) {
    return (c == 0) ? v.x : (c == 1) ? v.y : (c == 2) ? v.z : v.w;
}

struct __align__(16) SmemLayout {
    float B0[N_ANT * AP];
    float B1[N_ANT * AP];
    float B2[N_ANT * AP];
    float B3[N_ANT * AP];
    float Ws[3 * WCH];          // up to 3 fused weight chunks
    float Ss[N_ANT * SP];
    unsigned long long mb[N_ANT];
};

#define EPI_PLAIN  0
#define EPI_RELU   1
#define EPI_SIGADD 2   // C = sigmoid(acc + T)
#define EPI_TANHN  3   // C = tanh(T + R*acc)

// Fused multi-weight GEMM: for w in 0..NW-1:
//   C[w][64][128] = epi( A[64][KDIM] @ Wg[w][128][KDIM]^T + bg[w] )
// Thread map (512 thr): lane -> 4 cols (j0=4*lane), warp -> 4 tokens (t0=4*wrp).
// Staging map: js = tid&127 (weight row), kq = (tid>>7)*8 (k-octet) -> STS conflict-free.
template <int KDIM, int NW>
__device__ __noinline__ void gemm_multi(
    const float* __restrict__ A,
    const float* const* Wg, const float* const* bg,
    float* const* C, const float* const* T, const float* R,
    float* __restrict__ Ws, int tid, int mode)
{
    const int lane = tid & 31;
    const int wrp  = tid >> 5;
    const int j0   = lane * 4;
    const int t0   = wrp * 4;
    const int js   = tid & 127;
    const int kq   = (tid >> 7) * 8;

    const float* Wp[NW]; const float* bp[NW]; float* Cp[NW]; const float* Tp[NW];
#pragma unroll
    for (int w = 0; w < NW; w++) { Wp[w] = Wg[w]; bp[w] = bg[w]; Cp[w] = C[w]; Tp[w] = T[w]; }

    u64 acc[NW][4][2];
#pragma unroll
    for (int w = 0; w < NW; w++) {
        const float4 b4 = *reinterpret_cast<const float4*>(bp[w] + j0);
        const u64 b01 = pack2(b4.x, b4.y);
        const u64 b23 = pack2(b4.z, b4.w);
#pragma unroll
        for (int t = 0; t < 4; t++) { acc[w][t][0] = b01; acc[w][t][1] = b23; }
    }

    float4 stg[NW][2];
#pragma unroll
    for (int w = 0; w < NW; w++) {
        const float* src = Wp[w] + js * KDIM + kq;
        stg[w][0] = *reinterpret_cast<const float4*>(src);
        stg[w][1] = *reinterpret_cast<const float4*>(src + 4);
    }

    constexpr int NC = KDIM / 32;
#pragma unroll 1
    for (int c = 0; c < NC; c++) {
        __syncthreads();                       // previous users of Ws done
#pragma unroll
        for (int w = 0; w < NW; w++) {
#pragma unroll
            for (int e = 0; e < 8; e++) {
                const float v = (e < 4) ? f4c(stg[w][0], e) : f4c(stg[w][1], e - 4);
                Ws[w * WCH + (kq + e) * WP + js] = v;
            }
        }
        __syncthreads();
        if (c + 1 < NC) {                      // prefetch next chunk under compute
#pragma unroll
            for (int w = 0; w < NW; w++) {
                const float* src = Wp[w] + js * KDIM + (c + 1) * 32 + kq;
                stg[w][0] = *reinterpret_cast<const float4*>(src);
                stg[w][1] = *reinterpret_cast<const float4*>(src + 4);
            }
        }
        const int k0 = c * 32;
#pragma unroll 2
        for (int kb = 0; kb < 8; kb++) {
            float4 a4[4];
#pragma unroll
            for (int t = 0; t < 4; t++)
                a4[t] = *reinterpret_cast<const float4*>(A + (t0 + t) * AP + k0 + kb * 4);
#pragma unroll
            for (int q = 0; q < 4; q++) {
                u64 w01[NW], w23[NW];
#pragma unroll
                for (int w = 0; w < NW; w++) {
                    const float4 wv = *reinterpret_cast<const float4*>(
                        Ws + w * WCH + (kb * 4 + q) * WP + j0);
                    w01[w] = pack2(wv.x, wv.y);
                    w23[w] = pack2(wv.z, wv.w);
                }
#pragma unroll
                for (int t = 0; t < 4; t++) {
                    const u64 ad = dup2(f4c(a4[t], q));
#pragma unroll
                    for (int w = 0; w < NW; w++) {
                        acc[w][t][0] = ffma2(ad, w01[w], acc[w][t][0]);
                        acc[w][t][1] = ffma2(ad, w23[w], acc[w][t][1]);
                    }
                }
            }
        }
    }
    __syncthreads();   // all A/Ws reads done -> safe to write C even if C aliases A

#pragma unroll
    for (int w = 0; w < NW; w++) {
#pragma unroll
        for (int t = 0; t < 4; t++) {
            const int idx = (t0 + t) * AP + j0;
            const float2 v01 = unpack2(acc[w][t][0]);
            const float2 v23 = unpack2(acc[w][t][1]);
            float v[4] = {v01.x, v01.y, v23.x, v23.y};
            if (mode == EPI_RELU) {
#pragma unroll
                for (int j = 0; j < 4; j++) v[j] = fmaxf(v[j], 0.f);
            } else if (mode == EPI_SIGADD) {
                const float4 t4 = *reinterpret_cast<const float4*>(Tp[w] + idx);
                v[0] += t4.x; v[1] += t4.y; v[2] += t4.z; v[3] += t4.w;
#pragma unroll
                for (int j = 0; j < 4; j++) v[j] = 1.f / (1.f + __expf(-v[j]));
            } else if (mode == EPI_TANHN) {
                const float4 t4 = *reinterpret_cast<const float4*>(Tp[w] + idx);
                const float4 r4 = *reinterpret_cast<const float4*>(R + idx);
                v[0] = tanhf(t4.x + r4.x * v[0]);
                v[1] = tanhf(t4.y + r4.y * v[1]);
                v[2] = tanhf(t4.z + r4.z * v[2]);
                v[3] = tanhf(t4.w + r4.w * v[3]);
            }
            *reinterpret_cast<float4*>(Cp[w] + idx) = make_float4(v[0], v[1], v[2], v[3]);
        }
    }
    __syncthreads();
}

// Masked MHA core (512 threads).
__device__ __noinline__ void attention(
    const float* __restrict__ Q, const float* __restrict__ K,
    const float* __restrict__ V, float* __restrict__ O,
    float* __restrict__ Ss, const unsigned long long* __restrict__ mb, int tid)
{
    const float scale = 0.17677669529663687f;  // 1/sqrt(32)
    const int lane = tid & 31;
    const int wrp  = tid >> 5;
#pragma unroll 1
    for (int h = 0; h < 4; h++) {
        const int c0 = h * 32;
        // ---- scores: lane -> m in {lane, lane+32}; warp -> tokens t0..t0+3 ----
        {
            const int t0 = wrp * 4;
            u64 acc[2][2] = {{0ULL, 0ULL}, {0ULL, 0ULL}};
#pragma unroll 2
            for (int d0 = 0; d0 < 32; d0 += 4) {
                const float4 kl4 = *reinterpret_cast<const float4*>(K + lane * AP + c0 + d0);
                const float4 kh4 = *reinterpret_cast<const float4*>(K + (lane + 32) * AP + c0 + d0);
                float4 q4[4];
#pragma unroll
                for (int t = 0; t < 4; t++)
                    q4[t] = *reinterpret_cast<const float4*>(Q + (t0 + t) * AP + c0 + d0);
#pragma unroll
                for (int d = 0; d < 4; d++) {
                    const u64 kl = dup2(f4c(kl4, d));
                    const u64 kh = dup2(f4c(kh4, d));
#pragma unroll
                    for (int tp = 0; tp < 2; tp++) {
                        const u64 q2 = pack2(f4c(q4[2 * tp], d), f4c(q4[2 * tp + 1], d));
                        acc[tp][0] = ffma2(q2, kl, acc[tp][0]);
                        acc[tp][1] = ffma2(q2, kh, acc[tp][1]);
                    }
                }
            }
#pragma unroll
            for (int tp = 0; tp < 2; tp++) {
                const float2 lo = unpack2(acc[tp][0]);
                const float2 hi = unpack2(acc[tp][1]);
                Ss[(t0 + 2 * tp) * SP + lane]          = lo.x * scale;
                Ss[(t0 + 2 * tp + 1) * SP + lane]      = lo.y * scale;
                Ss[(t0 + 2 * tp) * SP + lane + 32]     = hi.x * scale;
                Ss[(t0 + 2 * tp + 1) * SP + lane + 32] = hi.y * scale;
            }
        }
        __syncthreads();
        // ---- masked softmax over m (8 threads per row) ----
        {
            const int t = tid >> 3;
            const int q = tid & 7;
            const unsigned long long bits = mb[t];
            float mx = -1e30f;
            for (int m = q; m < N_ANT; m += 8)
                if ((bits >> m) & 1ULL) mx = fmaxf(mx, Ss[t * SP + m]);
            mx = fmaxf(mx, __shfl_xor_sync(0xffffffffu, mx, 1));
            mx = fmaxf(mx, __shfl_xor_sync(0xffffffffu, mx, 2));
            mx = fmaxf(mx, __shfl_xor_sync(0xffffffffu, mx, 4));
            float sum = 0.f;
            for (int m = q; m < N_ANT; m += 8) {
                const float p = ((bits >> m) & 1ULL) ? __expf(Ss[t * SP + m] - mx) : 0.f;
                Ss[t * SP + m] = p;
                sum += p;
            }
            sum += __shfl_xor_sync(0xffffffffu, sum, 1);
            sum += __shfl_xor_sync(0xffffffffu, sum, 2);
            sum += __shfl_xor_sync(0xffffffffu, sum, 4);
            const float rinv = 1.f / sum;
            for (int m = q; m < N_ANT; m += 8) Ss[t * SP + m] *= rinv;
        }
        __syncthreads();
        // ---- O[:, c0:c0+32] = att @ V[:, c0:c0+32]: thread -> 1 token x 4 cols ----
        {
            const int d0 = (tid & 7) * 4;
            const int t  = tid >> 3;
            u64 oa0 = 0ULL, oa1 = 0ULL;
#pragma unroll 4
            for (int m = 0; m < N_ANT; m++) {
                const float4 vv = *reinterpret_cast<const float4*>(V + m * AP + c0 + d0);
                const u64 a0 = dup2(Ss[t * SP + m]);
                oa0 = ffma2(a0, pack2(vv.x, vv.y), oa0);
                oa1 = ffma2(a0, pack2(vv.z, vv.w), oa1);
            }
            const float2 o01 = unpack2(oa0);
            const float2 o23 = unpack2(oa1);
            *reinterpret_cast<float4*>(O + t * AP + c0 + d0) =
                make_float4(o01.x, o01.y, o23.x, o23.y);
        }
        __syncthreads();
    }
}

__global__ void __launch_bounds__(NTH, 1) drgn_kernel(
    const float* __restrict__ x, const int* __restrict__ mask,
    const float* __restrict__ hs,
    const float* __restrict__ enc_w, const float* __restrict__ enc_b,
    const float* __restrict__ q1_w, const float* __restrict__ q1_b,
    const float* __restrict__ k1_w, const float* __restrict__ k1_b,
    const float* __restrict__ v1_w, const float* __restrict__ v1_b,
    const float* __restrict__ o1_w, const float* __restrict__ o1_b,
    const float* __restrict__ q2_w, const float* __restrict__ q2_b,
    const float* __restrict__ k2_w, const float* __restrict__ k2_b,
    const float* __restrict__ v2_w, const float* __restrict__ v2_b,
    const float* __restrict__ o2_w, const float* __restrict__ o2_b,
    const float* __restrict__ w_ih, const float* __restrict__ w_hh,
    const float* __restrict__ b_ih, const float* __restrict__ b_hh,
    const float* __restrict__ lin_w, const float* __restrict__ lin_b,
    float* __restrict__ qs_out, float* __restrict__ h3_out, int act)
{
    extern __shared__ char smem_raw[];
    SmemLayout* s = reinterpret_cast<SmemLayout*>(smem_raw);
    const int tid = threadIdx.x;
    const int b   = blockIdx.x;

    // ---- load x tile and mask bitmap ----
    {
        const float* xb = x + (size_t)b * (N_ANT * 64);
        for (int idx = tid; idx < N_ANT * 64; idx += NTH)
            s->B0[(idx >> 6) * AP + (idx & 63)] = xb[idx];
        if (tid < N_ANT) {
            const int* mrow = mask + ((size_t)b * N_ANT + tid) * N_ANT;
            unsigned long long bits = 0ULL;
            for (int m = 0; m < N_ANT; m++)
                bits |= (unsigned long long)(mrow[m] != 0) << m;
            s->mb[tid] = bits;
        }
    }

    // ---- encoder: xe = relu(x @ enc_w^T) -> B1 ----
    {
        const float* W[1] = {enc_w}; const float* B[1] = {enc_b};
        float* Cc[1] = {s->B1};      const float* Tt[1] = {nullptr};
        gemm_multi<64, 1>(s->B0, W, B, Cc, Tt, nullptr, s->Ws, tid, EPI_RELU);
    }

    // ---- MHA layer 1: fused QKV from xe (B1) ----
    {
        const float* W[3] = {q1_w, k1_w, v1_w};
        const float* B[3] = {q1_b, k1_b, v1_b};
        float* Cc[3] = {s->B0, s->B2, s->B3};
        const float* Tt[3] = {nullptr, nullptr, nullptr};
        gemm_multi<128, 3>(s->B1, W, B, Cc, Tt, nullptr, s->Ws, tid, EPI_RELU);
    }
    attention(s->B0, s->B2, s->B3, s->B1, s->Ss, s->mb, tid);
    {
        const float* W[1] = {o1_w}; const float* B[1] = {o1_b};
        float* Cc[1] = {s->B0};     const float* Tt[1] = {nullptr};
        gemm_multi<128, 1>(s->B1, W, B, Cc, Tt, nullptr, s->Ws, tid, EPI_RELU);  // h1 -> B0
    }

    // ---- MHA layer 2: fused QKV from h1 (B0) ----
    {
        const float* W[3] = {q2_w, k2_w, v2_w};
        const float* B[3] = {q2_b, k2_b, v2_b};
        float* Cc[3] = {s->B1, s->B2, s->B3};
        const float* Tt[3] = {nullptr, nullptr, nullptr};
        gemm_multi<128, 3>(s->B0, W, B, Cc, Tt, nullptr, s->Ws, tid, EPI_RELU);
    }
    attention(s->B1, s->B2, s->B3, s->B0, s->Ss, s->mb, tid);
    {
        const float* W[1] = {o2_w}; const float* B[1] = {o2_b};
        float* Cc[1] = {s->B1};     const float* Tt[1] = {nullptr};
        gemm_multi<128, 1>(s->B0, W, B, Cc, Tt, nullptr, s->Ws, tid, EPI_RELU);  // h2 -> B1
    }

    // ---- load previous hidden state -> B2 ----
    {
        const float* hb = hs + (size_t)b * (N_ANT * HID);
        for (int idx = tid; idx < N_ANT * HID; idx += NTH)
            s->B2[(idx >> 7) * AP + (idx & 127)] = hb[idx];
    }

    // ---- GRU cell: h2 (B1), h (B2) ----
    {   // i_r -> B0, i_z -> B3  (fused, plain)
        const float* W[2] = {w_ih, w_ih + 128 * HID};
        const float* B[2] = {b_ih, b_ih + 128};
        float* Cc[2] = {s->B0, s->B3};
        const float* Tt[2] = {nullptr, nullptr};
        gemm_multi<128, 2>(s->B1, W, B, Cc, Tt, nullptr, s->Ws, tid, EPI_PLAIN);
    }
    {   // r = sig(i_r + h_r) -> B0 ; z = sig(i_z + h_z) -> B3  (fused)
        const float* W[2] = {w_hh, w_hh + 128 * HID};
        const float* B[2] = {b_hh, b_hh + 128};
        float* Cc[2] = {s->B0, s->B3};
        const float* Tt[2] = {s->B0, s->B3};
        gemm_multi<128, 2>(s->B2, W, B, Cc, Tt, nullptr, s->Ws, tid, EPI_SIGADD);
    }
    {   // i_n -> B1 (in place over h2; safe: sync precedes epilogue writes)
        const float* W[1] = {w_ih + 256 * HID}; const float* B[1] = {b_ih + 256};
        float* Cc[1] = {s->B1}; const float* Tt[1] = {nullptr};
        gemm_multi<128, 1>(s->B1, W, B, Cc, Tt, nullptr, s->Ws, tid, EPI_PLAIN);
    }
    {   // n = tanh(i_n + r * h_n) -> B1
        const float* W[1] = {w_hh + 256 * HID}; const float* B[1] = {b_hh + 256};
        float* Cc[1] = {s->B1}; const float* Tt[1] = {s->B1};
        gemm_multi<128, 1>(s->B2, W, B, Cc, Tt, s->B0, s->Ws, tid, EPI_TANHN);
    }

    // ---- h3 = (1-z)*n + z*h ; write h3 to gmem and keep in B1 ----
    {
        float* h3b = h3_out + (size_t)b * (N_ANT * HID);
        for (int idx = tid; idx < N_ANT * HID; idx += NTH) {
            const int off = (idx >> 7) * AP + (idx & 127);
            const float z  = s->B3[off];
            const float h3 = (1.f - z) * s->B1[off] + z * s->B2[off];
            s->B1[off] = h3;
            h3b[idx]   = h3;
        }
    }
    __syncthreads();

    // ---- qs = h3 @ lin_w^T + lin_b ----
    {
        float* qb = qs_out + (size_t)b * (N_ANT * act);
        for (int idx = tid; idx < N_ANT * act; idx += NTH) {
            const int t = idx / act;
            const int a = idx - t * act;
            const float* wr = lin_w + a * HID;
            float sacc = lin_b[a];
#pragma unroll 8
            for (int k = 0; k < HID; k++) sacc = fmaf(s->B1[t * AP + k], wr[k], sacc);
            qb[idx] = sacc;
        }
    }
}

extern "C" void kernel_launch(void* const* d_in, const int* in_sizes, int n_in,
                              void* d_out, int out_size)
{
    const float* x     = (const float*)d_in[0];
    const int*   mask  = (const int*)  d_in[1];
    const float* hs    = (const float*)d_in[2];
    const float* enc_w = (const float*)d_in[3];
    const float* enc_b = (const float*)d_in[4];
    const float* q1_w  = (const float*)d_in[5];
    const float* q1_b  = (const float*)d_in[6];
    const float* k1_w  = (const float*)d_in[7];
    const float* k1_b  = (const float*)d_in[8];
    const float* v1_w  = (const float*)d_in[9];
    const float* v1_b  = (const float*)d_in[10];
    const float* o1_w  = (const float*)d_in[11];
    const float* o1_b  = (const float*)d_in[12];
    const float* q2_w  = (const float*)d_in[13];
    const float* q2_b  = (const float*)d_in[14];
    const float* k2_w  = (const float*)d_in[15];
    const float* k2_b  = (const float*)d_in[16];
    const float* v2_w  = (const float*)d_in[17];
    const float* v2_b  = (const float*)d_in[18];
    const float* o2_w  = (const float*)d_in[19];
    const float* o2_b  = (const float*)d_in[20];
    const float* w_ih  = (const float*)d_in[21];
    const float* w_hh  = (const float*)d_in[22];
    const float* b_ih  = (const float*)d_in[23];
    const float* b_hh  = (const float*)d_in[24];
    const float* lin_w = (const float*)d_in[25];
    const float* lin_b = (const float*)d_in[26];

    const int bs  = in_sizes[0] / (N_ANT * 64);
    const int act = in_sizes[25] / HID;  // 20

    float* qs = (float*)d_out;
    float* h3 = qs + (size_t)bs * N_ANT * act;

    const int smem_bytes = (int)sizeof(SmemLayout);
    cudaFuncSetAttribute(drgn_kernel, cudaFuncAttributeMaxDynamicSharedMemorySize, smem_bytes);

    drgn_kernel<<<bs, NTH, smem_bytes>>>(
        x, mask, hs, enc_w, enc_b,
        q1_w, q1_b, k1_w, k1_b, v1_w, v1_b, o1_w, o1_b,
        q2_w, q2_b, k2_w, k2_b, v2_w, v2_b, o2_w, o2_b,
        w_ih, w_hh, b_ih, b_hh, lin_w, lin_b,
        qs, h3, act);
}

// round 5
// speedup vs baseline: 1.1296x; 1.1296x over previous
#include <cuda_runtime.h>
#include <math.h>

#define N_ANT 64
#define HID   128
#define AP    132   // activation pitch (floats): 16B-aligned rows
#define WP    132   // staged-weight pitch
#define WCH   (32 * WP)
#define SP    65    // score pitch
#define NTH   512

typedef unsigned long long u64;

__device__ __forceinline__ u64 pack2(float lo, float hi) {
    u64 r; asm("mov.b64 %0,{%1,%2};" : "=l"(r) : "f"(lo), "f"(hi)); return r;
}
__device__ __forceinline__ u64 dup2(float v) { return pack2(v, v); }
__device__ __forceinline__ u64 ffma2(u64 a, u64 b, u64 c) {
    u64 d; asm("fma.rn.f32x2 %0,%1,%2,%3;" : "=l"(d) : "l"(a), "l"(b), "l"(c)); return d;
}
__device__ __forceinline__ float2 unpack2(u64 p) {
    float2 f; asm("mov.b64 {%0,%1},%2;" : "=f"(f.x), "=f"(f.y) : "l"(p)); return f;
}
__device__ __forceinline__ float f4c(const float4& v, int c) {
    return (c == 0) ? v.x : (c == 1) ? v.y : (c == 2) ? v.z : v.w;
}

struct __align__(16) SmemLayout {
    float B0[N_ANT * AP];
    float B1[N_ANT * AP];
    float B2[N_ANT * AP];
    float B3[N_ANT * AP];
    float Ws[3 * WCH];          // up to 3 fused weight chunks
    float Ss[N_ANT * SP];
    unsigned long long mb[N_ANT];
};

#define EPI_PLAIN  0
#define EPI_RELU   1
#define EPI_SIGADD 2   // C = sigmoid(acc + T)
#define EPI_TANHN  3   // C = tanh(T + R*acc)

// Fused multi-weight GEMM: for w in 0..NW-1:
//   C[w][64][128] = epi( A[64][KDIM] @ Wg[w][128][KDIM]^T + bg[w] )
// Thread map (512 thr): lane -> 4 cols (j0=4*lane), warp -> 4 tokens (t0=4*wrp).
// Staging map: js = tid&127 (weight row), kq = (tid>>7)*8 (k-octet) -> STS conflict-free.
template <int KDIM, int NW>
__device__ __noinline__ void gemm_multi(
    const float* __restrict__ A,
    const float* const* Wg, const float* const* bg,
    float* const* C, const float* const* T, const float* R,
    float* __restrict__ Ws, int tid, int mode)
{
    const int lane = tid & 31;
    const int wrp  = tid >> 5;
    const int j0   = lane * 4;
    const int t0   = wrp * 4;
    const int js   = tid & 127;
    const int kq   = (tid >> 7) * 8;

    const float* Wp[NW]; const float* bp[NW]; float* Cp[NW]; const float* Tp[NW];
#pragma unroll
    for (int w = 0; w < NW; w++) { Wp[w] = Wg[w]; bp[w] = bg[w]; Cp[w] = C[w]; Tp[w] = T[w]; }

    u64 acc[NW][4][2];
#pragma unroll
    for (int w = 0; w < NW; w++) {
        const float4 b4 = *reinterpret_cast<const float4*>(bp[w] + j0);
        const u64 b01 = pack2(b4.x, b4.y);
        const u64 b23 = pack2(b4.z, b4.w);
#pragma unroll
        for (int t = 0; t < 4; t++) { acc[w][t][0] = b01; acc[w][t][1] = b23; }
    }

    float4 stg[NW][2];
#pragma unroll
    for (int w = 0; w < NW; w++) {
        const float* src = Wp[w] + js * KDIM + kq;
        stg[w][0] = *reinterpret_cast<const float4*>(src);
        stg[w][1] = *reinterpret_cast<const float4*>(src + 4);
    }

    constexpr int NC = KDIM / 32;
#pragma unroll 1
    for (int c = 0; c < NC; c++) {
        __syncthreads();                       // previous users of Ws done
#pragma unroll
        for (int w = 0; w < NW; w++) {
#pragma unroll
            for (int e = 0; e < 8; e++) {
                const float v = (e < 4) ? f4c(stg[w][0], e) : f4c(stg[w][1], e - 4);
                Ws[w * WCH + (kq + e) * WP + js] = v;
            }
        }
        __syncthreads();
        if (c + 1 < NC) {                      // prefetch next chunk under compute
#pragma unroll
            for (int w = 0; w < NW; w++) {
                const float* src = Wp[w] + js * KDIM + (c + 1) * 32 + kq;
                stg[w][0] = *reinterpret_cast<const float4*>(src);
                stg[w][1] = *reinterpret_cast<const float4*>(src + 4);
            }
        }
        const int k0 = c * 32;
#pragma unroll 2
        for (int kb = 0; kb < 8; kb++) {
            float4 a4[4];
#pragma unroll
            for (int t = 0; t < 4; t++)
                a4[t] = *reinterpret_cast<const float4*>(A + (t0 + t) * AP + k0 + kb * 4);
#pragma unroll
            for (int q = 0; q < 4; q++) {
                u64 w01[NW], w23[NW];
#pragma unroll
                for (int w = 0; w < NW; w++) {
                    const float4 wv = *reinterpret_cast<const float4*>(
                        Ws + w * WCH + (kb * 4 + q) * WP + j0);
                    w01[w] = pack2(wv.x, wv.y);
                    w23[w] = pack2(wv.z, wv.w);
                }
#pragma unroll
                for (int t = 0; t < 4; t++) {
                    const u64 ad = dup2(f4c(a4[t], q));
#pragma unroll
                    for (int w = 0; w < NW; w++) {
                        acc[w][t][0] = ffma2(ad, w01[w], acc[w][t][0]);
                        acc[w][t][1] = ffma2(ad, w23[w], acc[w][t][1]);
                    }
                }
            }
        }
    }
    __syncthreads();   // all A/Ws reads done -> safe to write C even if C aliases A

#pragma unroll
    for (int w = 0; w < NW; w++) {
#pragma unroll
        for (int t = 0; t < 4; t++) {
            const int idx = (t0 + t) * AP + j0;
            const float2 v01 = unpack2(acc[w][t][0]);
            const float2 v23 = unpack2(acc[w][t][1]);
            float v[4] = {v01.x, v01.y, v23.x, v23.y};
            if (mode == EPI_RELU) {
#pragma unroll
                for (int j = 0; j < 4; j++) v[j] = fmaxf(v[j], 0.f);
            } else if (mode == EPI_SIGADD) {
                const float4 t4 = *reinterpret_cast<const float4*>(Tp[w] + idx);
                v[0] += t4.x; v[1] += t4.y; v[2] += t4.z; v[3] += t4.w;
#pragma unroll
                for (int j = 0; j < 4; j++) v[j] = 1.f / (1.f + __expf(-v[j]));
            } else if (mode == EPI_TANHN) {
                const float4 t4 = *reinterpret_cast<const float4*>(Tp[w] + idx);
                const float4 r4 = *reinterpret_cast<const float4*>(R + idx);
                v[0] = tanhf(t4.x + r4.x * v[0]);
                v[1] = tanhf(t4.y + r4.y * v[1]);
                v[2] = tanhf(t4.z + r4.z * v[2]);
                v[3] = tanhf(t4.w + r4.w * v[3]);
            }
            *reinterpret_cast<float4*>(Cp[w] + idx) = make_float4(v[0], v[1], v[2], v[3]);
        }
    }
    __syncthreads();
}

// Masked MHA core (512 threads).
__device__ __noinline__ void attention(
    const float* __restrict__ Q, const float* __restrict__ K,
    const float* __restrict__ V, float* __restrict__ O,
    float* __restrict__ Ss, const unsigned long long* __restrict__ mb, int tid)
{
    const float scale = 0.17677669529663687f;  // 1/sqrt(32)
    const int lane = tid & 31;
    const int wrp  = tid >> 5;
#pragma unroll 1
    for (int h = 0; h < 4; h++) {
        const int c0 = h * 32;
        // ---- scores: lane -> m in {lane, lane+32}; warp -> tokens t0..t0+3 ----
        {
            const int t0 = wrp * 4;
            u64 acc[2][2] = {{0ULL, 0ULL}, {0ULL, 0ULL}};
#pragma unroll 2
            for (int d0 = 0; d0 < 32; d0 += 4) {
                const float4 kl4 = *reinterpret_cast<const float4*>(K + lane * AP + c0 + d0);
                const float4 kh4 = *reinterpret_cast<const float4*>(K + (lane + 32) * AP + c0 + d0);
                float4 q4[4];
#pragma unroll
                for (int t = 0; t < 4; t++)
                    q4[t] = *reinterpret_cast<const float4*>(Q + (t0 + t) * AP + c0 + d0);
#pragma unroll
                for (int d = 0; d < 4; d++) {
                    const u64 kl = dup2(f4c(kl4, d));
                    const u64 kh = dup2(f4c(kh4, d));
#pragma unroll
                    for (int tp = 0; tp < 2; tp++) {
                        const u64 q2 = pack2(f4c(q4[2 * tp], d), f4c(q4[2 * tp + 1], d));
                        acc[tp][0] = ffma2(q2, kl, acc[tp][0]);
                        acc[tp][1] = ffma2(q2, kh, acc[tp][1]);
                    }
                }
            }
#pragma unroll
            for (int tp = 0; tp < 2; tp++) {
                const float2 lo = unpack2(acc[tp][0]);
                const float2 hi = unpack2(acc[tp][1]);
                Ss[(t0 + 2 * tp) * SP + lane]          = lo.x * scale;
                Ss[(t0 + 2 * tp + 1) * SP + lane]      = lo.y * scale;
                Ss[(t0 + 2 * tp) * SP + lane + 32]     = hi.x * scale;
                Ss[(t0 + 2 * tp + 1) * SP + lane + 32] = hi.y * scale;
            }
        }
        __syncthreads();
        // ---- masked softmax over m (8 threads per row) ----
        {
            const int t = tid >> 3;
            const int q = tid & 7;
            const unsigned long long bits = mb[t];
            float mx = -1e30f;
            for (int m = q; m < N_ANT; m += 8)
                if ((bits >> m) & 1ULL) mx = fmaxf(mx, Ss[t * SP + m]);
            mx = fmaxf(mx, __shfl_xor_sync(0xffffffffu, mx, 1));
            mx = fmaxf(mx, __shfl_xor_sync(0xffffffffu, mx, 2));
            mx = fmaxf(mx, __shfl_xor_sync(0xffffffffu, mx, 4));
            float sum = 0.f;
            for (int m = q; m < N_ANT; m += 8) {
                const float p = ((bits >> m) & 1ULL) ? __expf(Ss[t * SP + m] - mx) : 0.f;
                Ss[t * SP + m] = p;
                sum += p;
            }
            sum += __shfl_xor_sync(0xffffffffu, sum, 1);
            sum += __shfl_xor_sync(0xffffffffu, sum, 2);
            sum += __shfl_xor_sync(0xffffffffu, sum, 4);
            const float rinv = 1.f / sum;
            for (int m = q; m < N_ANT; m += 8) Ss[t * SP + m] *= rinv;
        }
        __syncthreads();
        // ---- O[:, c0:c0+32] = att @ V[:, c0:c0+32]: thread -> 1 token x 4 cols ----
        {
            const int d0 = (tid & 7) * 4;
            const int t  = tid >> 3;
            u64 oa0 = 0ULL, oa1 = 0ULL;
#pragma unroll 4
            for (int m = 0; m < N_ANT; m++) {
                const float4 vv = *reinterpret_cast<const float4*>(V + m * AP + c0 + d0);
                const u64 a0 = dup2(Ss[t * SP + m]);
                oa0 = ffma2(a0, pack2(vv.x, vv.y), oa0);
                oa1 = ffma2(a0, pack2(vv.z, vv.w), oa1);
            }
            const float2 o01 = unpack2(oa0);
            const float2 o23 = unpack2(oa1);
            *reinterpret_cast<float4*>(O + t * AP + c0 + d0) =
                make_float4(o01.x, o01.y, o23.x, o23.y);
        }
        __syncthreads();
    }
}

__global__ void __launch_bounds__(NTH, 1) drgn_kernel(
    const float* __restrict__ x, const int* __restrict__ mask,
    const float* __restrict__ hs,
    const float* __restrict__ enc_w, const float* __restrict__ enc_b,
    const float* __restrict__ q1_w, const float* __restrict__ q1_b,
    const float* __restrict__ k1_w, const float* __restrict__ k1_b,
    const float* __restrict__ v1_w, const float* __restrict__ v1_b,
    const float* __restrict__ o1_w, const float* __restrict__ o1_b,
    const float* __restrict__ q2_w, const float* __restrict__ q2_b,
    const float* __restrict__ k2_w, const float* __restrict__ k2_b,
    const float* __restrict__ v2_w, const float* __restrict__ v2_b,
    const float* __restrict__ o2_w, const float* __restrict__ o2_b,
    const float* __restrict__ w_ih, const float* __restrict__ w_hh,
    const float* __restrict__ b_ih, const float* __restrict__ b_hh,
    const float* __restrict__ lin_w, const float* __restrict__ lin_b,
    float* __restrict__ qs_out, float* __restrict__ h3_out, int act)
{
    extern __shared__ char smem_raw[];
    SmemLayout* s = reinterpret_cast<SmemLayout*>(smem_raw);
    const int tid = threadIdx.x;
    const int b   = blockIdx.x;

    // ---- load x tile and mask bitmap ----
    {
        const float* xb = x + (size_t)b * (N_ANT * 64);
        for (int idx = tid; idx < N_ANT * 64; idx += NTH)
            s->B0[(idx >> 6) * AP + (idx & 63)] = xb[idx];
        if (tid < N_ANT) {
            const int* mrow = mask + ((size_t)b * N_ANT + tid) * N_ANT;
            unsigned long long bits = 0ULL;
            for (int m = 0; m < N_ANT; m++)
                bits |= (unsigned long long)(mrow[m] != 0) << m;
            s->mb[tid] = bits;
        }
    }

    // ---- encoder: xe = relu(x @ enc_w^T) -> B1 ----
    {
        const float* W[1] = {enc_w}; const float* B[1] = {enc_b};
        float* Cc[1] = {s->B1};      const float* Tt[1] = {nullptr};
        gemm_multi<64, 1>(s->B0, W, B, Cc, Tt, nullptr, s->Ws, tid, EPI_RELU);
    }

    // ---- MHA layer 1: fused QKV from xe (B1) ----
    {
        const float* W[3] = {q1_w, k1_w, v1_w};
        const float* B[3] = {q1_b, k1_b, v1_b};
        float* Cc[3] = {s->B0, s->B2, s->B3};
        const float* Tt[3] = {nullptr, nullptr, nullptr};
        gemm_multi<128, 3>(s->B1, W, B, Cc, Tt, nullptr, s->Ws, tid, EPI_RELU);
    }
    attention(s->B0, s->B2, s->B3, s->B1, s->Ss, s->mb, tid);
    {
        const float* W[1] = {o1_w}; const float* B[1] = {o1_b};
        float* Cc[1] = {s->B0};     const float* Tt[1] = {nullptr};
        gemm_multi<128, 1>(s->B1, W, B, Cc, Tt, nullptr, s->Ws, tid, EPI_RELU);  // h1 -> B0
    }

    // ---- MHA layer 2: fused QKV from h1 (B0) ----
    {
        const float* W[3] = {q2_w, k2_w, v2_w};
        const float* B[3] = {q2_b, k2_b, v2_b};
        float* Cc[3] = {s->B1, s->B2, s->B3};
        const float* Tt[3] = {nullptr, nullptr, nullptr};
        gemm_multi<128, 3>(s->B0, W, B, Cc, Tt, nullptr, s->Ws, tid, EPI_RELU);
    }
    attention(s->B1, s->B2, s->B3, s->B0, s->Ss, s->mb, tid);
    {
        const float* W[1] = {o2_w}; const float* B[1] = {o2_b};
        float* Cc[1] = {s->B1};     const float* Tt[1] = {nullptr};
        gemm_multi<128, 1>(s->B0, W, B, Cc, Tt, nullptr, s->Ws, tid, EPI_RELU);  // h2 -> B1
    }

    // ---- load previous hidden state -> B2 ----
    {
        const float* hb = hs + (size_t)b * (N_ANT * HID);
        for (int idx = tid; idx < N_ANT * HID; idx += NTH)
            s->B2[(idx >> 7) * AP + (idx & 127)] = hb[idx];
    }

    // ---- GRU cell: h2 (B1), h (B2) ----
    {   // i_r -> B0, i_z -> B3  (fused, plain)
        const float* W[2] = {w_ih, w_ih + 128 * HID};
        const float* B[2] = {b_ih, b_ih + 128};
        float* Cc[2] = {s->B0, s->B3};
        const float* Tt[2] = {nullptr, nullptr};
        gemm_multi<128, 2>(s->B1, W, B, Cc, Tt, nullptr, s->Ws, tid, EPI_PLAIN);
    }
    {   // r = sig(i_r + h_r) -> B0 ; z = sig(i_z + h_z) -> B3  (fused)
        const float* W[2] = {w_hh, w_hh + 128 * HID};
        const float* B[2] = {b_hh, b_hh + 128};
        float* Cc[2] = {s->B0, s->B3};
        const float* Tt[2] = {s->B0, s->B3};
        gemm_multi<128, 2>(s->B2, W, B, Cc, Tt, nullptr, s->Ws, tid, EPI_SIGADD);
    }
    {   // i_n -> B1 (in place over h2; safe: sync precedes epilogue writes)
        const float* W[1] = {w_ih + 256 * HID}; const float* B[1] = {b_ih + 256};
        float* Cc[1] = {s->B1}; const float* Tt[1] = {nullptr};
        gemm_multi<128, 1>(s->B1, W, B, Cc, Tt, nullptr, s->Ws, tid, EPI_PLAIN);
    }
    {   // n = tanh(i_n + r * h_n) -> B1
        const float* W[1] = {w_hh + 256 * HID}; const float* B[1] = {b_hh + 256};
        float* Cc[1] = {s->B1}; const float* Tt[1] = {s->B1};
        gemm_multi<128, 1>(s->B2, W, B, Cc, Tt, s->B0, s->Ws, tid, EPI_TANHN);
    }

    // ---- h3 = (1-z)*n + z*h ; write h3 to gmem and keep in B1 ----
    {
        float* h3b = h3_out + (size_t)b * (N_ANT * HID);
        for (int idx = tid; idx < N_ANT * HID; idx += NTH) {
            const int off = (idx >> 7) * AP + (idx & 127);
            const float z  = s->B3[off];
            const float h3 = (1.f - z) * s->B1[off] + z * s->B2[off];
            s->B1[off] = h3;
            h3b[idx]   = h3;
        }
    }
    __syncthreads();

    // ---- qs = h3 @ lin_w^T + lin_b (float4 over k) ----
    {
        float* qb = qs_out + (size_t)b * (N_ANT * act);
        for (int idx = tid; idx < N_ANT * act; idx += NTH) {
            const int t = idx / act;
            const int a = idx - t * act;
            const float* wr = lin_w + a * HID;
            const float* hr = s->B1 + t * AP;
            float sacc = lin_b[a];
#pragma unroll 8
            for (int k = 0; k < HID; k += 4) {
                const float4 h4 = *reinterpret_cast<const float4*>(hr + k);
                const float4 w4 = *reinterpret_cast<const float4*>(wr + k);
                sacc = fmaf(h4.x, w4.x, sacc);
                sacc = fmaf(h4.y, w4.y, sacc);
                sacc = fmaf(h4.z, w4.z, sacc);
                sacc = fmaf(h4.w, w4.w, sacc);
            }
            qb[idx] = sacc;
        }
    }
}

extern "C" void kernel_launch(void* const* d_in, const int* in_sizes, int n_in,
                              void* d_out, int out_size)
{
    const float* x     = (const float*)d_in[0];
    const int*   mask  = (const int*)  d_in[1];
    const float* hs    = (const float*)d_in[2];
    const float* enc_w = (const float*)d_in[3];
    const float* enc_b = (const float*)d_in[4];
    const float* q1_w  = (const float*)d_in[5];
    const float* q1_b  = (const float*)d_in[6];
    const float* k1_w  = (const float*)d_in[7];
    const float* k1_b  = (const float*)d_in[8];
    const float* v1_w  = (const float*)d_in[9];
    const float* v1_b  = (const float*)d_in[10];
    const float* o1_w  = (const float*)d_in[11];
    const float* o1_b  = (const float*)d_in[12];
    const float* q2_w  = (const float*)d_in[13];
    const float* q2_b  = (const float*)d_in[14];
    const float* k2_w  = (const float*)d_in[15];
    const float* k2_b  = (const float*)d_in[16];
    const float* v2_w  = (const float*)d_in[17];
    const float* v2_b  = (const float*)d_in[18];
    const float* o2_w  = (const float*)d_in[19];
    const float* o2_b  = (const float*)d_in[20];
    const float* w_ih  = (const float*)d_in[21];
    const float* w_hh  = (const float*)d_in[22];
    const float* b_ih  = (const float*)d_in[23];
    const float* b_hh  = (const float*)d_in[24];
    const float* lin_w = (const float*)d_in[25];
    const float* lin_b = (const float*)d_in[26];

    const int bs  = in_sizes[0] / (N_ANT * 64);
    const int act = in_sizes[25] / HID;  // 20

    float* qs = (float*)d_out;
    float* h3 = qs + (size_t)bs * N_ANT * act;

    const int smem_bytes = (int)sizeof(SmemLayout);
    cudaFuncSetAttribute(drgn_kernel, cudaFuncAttributeMaxDynamicSharedMemorySize, smem_bytes);

    drgn_kernel<<<bs, NTH, smem_bytes>>>(
        x, mask, hs, enc_w, enc_b,
        q1_w, q1_b, k1_w, k1_b, v1_w, v1_b, o1_w, o1_b,
        q2_w, q2_b, k2_w, k2_b, v2_w, v2_b, o2_w, o2_b,
        w_ih, w_hh, b_ih, b_hh, lin_w, lin_b,
        qs, h3, act);
}

// round 6
// speedup vs baseline: 1.8208x; 1.6119x over previous
#include <cuda_runtime.h>
#include <math.h>

#define N_ANT 64
#define HID   128
#define AP    132   // activation pitch: AP%32==4 -> A-fragment LDS conflict-free
#define WP    136   // staged-weight pitch: WP%32==8 -> B-fragment LDS conflict-free
#define WCH   (32 * WP)
#define SP    68    // score pitch: SP%32==4 -> P-fragment LDS conflict-free
#define NTH   512

__device__ __forceinline__ unsigned cvt_tf32(float v) {
    unsigned r; asm("cvt.rna.tf32.f32 %0, %1;" : "=r"(r) : "f"(v)); return r;
}
__device__ __forceinline__ void mma8(float& d0, float& d1, float& d2, float& d3,
                                     unsigned a0, unsigned a1, unsigned a2, unsigned a3,
                                     unsigned b0, unsigned b1) {
    asm("mma.sync.aligned.m16n8k8.row.col.f32.tf32.tf32.f32 "
        "{%0,%1,%2,%3},{%4,%5,%6,%7},{%8,%9},{%0,%1,%2,%3};"
        : "+f"(d0), "+f"(d1), "+f"(d2), "+f"(d3)
        : "r"(a0), "r"(a1), "r"(a2), "r"(a3), "r"(b0), "r"(b1));
}
__device__ __forceinline__ float f4c(const float4& v, int c) {
    return (c == 0) ? v.x : (c == 1) ? v.y : (c == 2) ? v.z : v.w;
}

struct __align__(16) SmemLayout {
    float B0[N_ANT * AP];
    float B1[N_ANT * AP];
    float B2[N_ANT * AP];
    float B3[N_ANT * AP];
    float Ws[3 * WCH];          // up to 3 fused weight chunks (k-major, tf32-rounded)
    float Ss[N_ANT * SP];
    unsigned long long mb[N_ANT];
};

#define EPI_PLAIN  0
#define EPI_RELU   1
#define EPI_SIGADD 2   // C = sigmoid(acc + T)
#define EPI_TANHN  3   // C = tanh(T + R*acc)

// Fused multi-weight GEMM on tf32 mma.sync:
//   C[w][64][128] = epi( A[64][KDIM] @ Wg[w][128][KDIM]^T + bg[w] )
// Warp tiling: mi = wrp&3 -> rows mi*16..+15 ; ni = wrp>>2 -> cols ni*32..+31 (4 n8 tiles).
// Fragment coords (m16n8k8): g = lane>>2, tg = lane&3.
template <int KDIM, int NW>
__device__ __noinline__ void gemm_mma(
    const float* __restrict__ A,
    const float* const* Wg, const float* const* bg,
    float* const* C, const float* const* T, const float* R,
    float* __restrict__ Ws, int tid, int mode)
{
    const int lane = tid & 31;
    const int wrp  = tid >> 5;
    const int g    = lane >> 2;
    const int tg   = lane & 3;
    const int mi   = wrp & 3;
    const int ni   = wrp >> 2;
    const int r0   = mi * 16 + g;
    const int r1   = r0 + 8;
    const int js   = tid & 127;          // weight output-row for staging
    const int kq   = (tid >> 7) * 8;     // k-octet for staging

    const float* Wp[NW]; const float* bp[NW]; float* Cp[NW]; const float* Tp[NW];
#pragma unroll
    for (int w = 0; w < NW; w++) { Wp[w] = Wg[w]; bp[w] = bg[w]; Cp[w] = C[w]; Tp[w] = T[w]; }

    // D fragments, bias-initialized. d[w][nt]: {(r0,j),(r0,j+1),(r1,j),(r1,j+1)}, j=ni*32+nt*8+2*tg
    float d[NW][4][4];
#pragma unroll
    for (int w = 0; w < NW; w++)
#pragma unroll
        for (int nt = 0; nt < 4; nt++) {
            const int j = ni * 32 + nt * 8 + 2 * tg;
            const float bb0 = bp[w][j];
            const float bb1 = bp[w][j + 1];
            d[w][nt][0] = bb0; d[w][nt][1] = bb1;
            d[w][nt][2] = bb0; d[w][nt][3] = bb1;
        }

    float4 stg[NW][2];
#pragma unroll
    for (int w = 0; w < NW; w++) {
        const float* src = Wp[w] + js * KDIM + kq;
        stg[w][0] = *reinterpret_cast<const float4*>(src);
        stg[w][1] = *reinterpret_cast<const float4*>(src + 4);
    }

    constexpr int NC = KDIM / 32;
#pragma unroll 1
    for (int c = 0; c < NC; c++) {
        __syncthreads();                       // previous users of Ws done
#pragma unroll
        for (int w = 0; w < NW; w++) {
#pragma unroll
            for (int e = 0; e < 8; e++) {
                const float v = (e < 4) ? f4c(stg[w][0], e) : f4c(stg[w][1], e - 4);
                Ws[w * WCH + (kq + e) * WP + js] = __uint_as_float(cvt_tf32(v));
            }
        }
        __syncthreads();
        if (c + 1 < NC) {                      // prefetch next chunk under compute
#pragma unroll
            for (int w = 0; w < NW; w++) {
                const float* src = Wp[w] + js * KDIM + (c + 1) * 32 + kq;
                stg[w][0] = *reinterpret_cast<const float4*>(src);
                stg[w][1] = *reinterpret_cast<const float4*>(src + 4);
            }
        }
#pragma unroll
        for (int ks = 0; ks < 4; ks++) {       // four k8 steps per chunk
            const int kk = c * 32 + ks * 8;
            const unsigned a0 = cvt_tf32(A[r0 * AP + kk + tg]);
            const unsigned a1 = cvt_tf32(A[r1 * AP + kk + tg]);
            const unsigned a2 = cvt_tf32(A[r0 * AP + kk + tg + 4]);
            const unsigned a3 = cvt_tf32(A[r1 * AP + kk + tg + 4]);
#pragma unroll
            for (int w = 0; w < NW; w++) {
#pragma unroll
                for (int nt = 0; nt < 4; nt++) {
                    const int n = ni * 32 + nt * 8 + g;
                    const unsigned b0 = __float_as_uint(Ws[w * WCH + (ks * 8 + tg) * WP + n]);
                    const unsigned b1 = __float_as_uint(Ws[w * WCH + (ks * 8 + tg + 4) * WP + n]);
                    mma8(d[w][nt][0], d[w][nt][1], d[w][nt][2], d[w][nt][3],
                         a0, a1, a2, a3, b0, b1);
                }
            }
        }
    }
    __syncthreads();   // all A/Ws reads done -> safe to write C even if C aliases A

#pragma unroll
    for (int w = 0; w < NW; w++) {
#pragma unroll
        for (int nt = 0; nt < 4; nt++) {
            const int j = ni * 32 + nt * 8 + 2 * tg;
            float v0 = d[w][nt][0], v1 = d[w][nt][1];
            float v2 = d[w][nt][2], v3 = d[w][nt][3];
            if (mode == EPI_RELU) {
                v0 = fmaxf(v0, 0.f); v1 = fmaxf(v1, 0.f);
                v2 = fmaxf(v2, 0.f); v3 = fmaxf(v3, 0.f);
            } else if (mode == EPI_SIGADD) {
                v0 += Tp[w][r0 * AP + j];     v1 += Tp[w][r0 * AP + j + 1];
                v2 += Tp[w][r1 * AP + j];     v3 += Tp[w][r1 * AP + j + 1];
                v0 = 1.f / (1.f + __expf(-v0)); v1 = 1.f / (1.f + __expf(-v1));
                v2 = 1.f / (1.f + __expf(-v2)); v3 = 1.f / (1.f + __expf(-v3));
            } else if (mode == EPI_TANHN) {
                v0 = tanhf(Tp[w][r0 * AP + j]     + R[r0 * AP + j]     * v0);
                v1 = tanhf(Tp[w][r0 * AP + j + 1] + R[r0 * AP + j + 1] * v1);
                v2 = tanhf(Tp[w][r1 * AP + j]     + R[r1 * AP + j]     * v2);
                v3 = tanhf(Tp[w][r1 * AP + j + 1] + R[r1 * AP + j + 1] * v3);
            }
            *reinterpret_cast<float2*>(Cp[w] + r0 * AP + j) = make_float2(v0, v1);
            *reinterpret_cast<float2*>(Cp[w] + r1 * AP + j) = make_float2(v2, v3);
        }
    }
    __syncthreads();
}

// Masked MHA core on tf32 mma (512 threads).
__device__ __noinline__ void attention_mma(
    const float* __restrict__ Q, const float* __restrict__ K,
    const float* __restrict__ V, float* __restrict__ O,
    float* __restrict__ Ss, const unsigned long long* __restrict__ mb, int tid)
{
    const float scale = 0.17677669529663687f;  // 1/sqrt(32)
    const int lane = tid & 31;
    const int wrp  = tid >> 5;
    const int g    = lane >> 2;
    const int tg   = lane & 3;
    const int mi   = wrp & 3;
    const int r0   = mi * 16 + g;
    const int r1   = r0 + 8;
#pragma unroll 1
    for (int h = 0; h < 4; h++) {
        const int c0 = h * 32;
        // ---- scores: S = scale * Q_h @ K_h^T   (M=64, N=64, K=32) ----
        {
            const int nj = wrp >> 2;             // 2 n8-tiles at nj*16
            float sd[2][4] = {{0.f,0.f,0.f,0.f},{0.f,0.f,0.f,0.f}};
#pragma unroll
            for (int ks = 0; ks < 4; ks++) {
                const int kk = c0 + ks * 8;
                const unsigned a0 = cvt_tf32(Q[r0 * AP + kk + tg]);
                const unsigned a1 = cvt_tf32(Q[r1 * AP + kk + tg]);
                const unsigned a2 = cvt_tf32(Q[r0 * AP + kk + tg + 4]);
                const unsigned a3 = cvt_tf32(Q[r1 * AP + kk + tg + 4]);
#pragma unroll
                for (int u = 0; u < 2; u++) {
                    const int n0 = nj * 16 + u * 8;
                    const unsigned b0 = cvt_tf32(K[(n0 + g) * AP + kk + tg]);
                    const unsigned b1 = cvt_tf32(K[(n0 + g) * AP + kk + tg + 4]);
                    mma8(sd[u][0], sd[u][1], sd[u][2], sd[u][3], a0, a1, a2, a3, b0, b1);
                }
            }
#pragma unroll
            for (int u = 0; u < 2; u++) {
                const int n = nj * 16 + u * 8 + 2 * tg;
                Ss[r0 * SP + n]     = sd[u][0] * scale;
                Ss[r0 * SP + n + 1] = sd[u][1] * scale;
                Ss[r1 * SP + n]     = sd[u][2] * scale;
                Ss[r1 * SP + n + 1] = sd[u][3] * scale;
            }
        }
        __syncthreads();
        // ---- masked softmax over keys (8 threads per row) ----
        {
            const int t = tid >> 3;
            const int q = tid & 7;
            const unsigned long long bits = mb[t];
            float mx = -1e30f;
            for (int m = q; m < N_ANT; m += 8)
                if ((bits >> m) & 1ULL) mx = fmaxf(mx, Ss[t * SP + m]);
            mx = fmaxf(mx, __shfl_xor_sync(0xffffffffu, mx, 1));
            mx = fmaxf(mx, __shfl_xor_sync(0xffffffffu, mx, 2));
            mx = fmaxf(mx, __shfl_xor_sync(0xffffffffu, mx, 4));
            float sum = 0.f;
            for (int m = q; m < N_ANT; m += 8) {
                const float p = ((bits >> m) & 1ULL) ? __expf(Ss[t * SP + m] - mx) : 0.f;
                Ss[t * SP + m] = p;
                sum += p;
            }
            sum += __shfl_xor_sync(0xffffffffu, sum, 1);
            sum += __shfl_xor_sync(0xffffffffu, sum, 2);
            sum += __shfl_xor_sync(0xffffffffu, sum, 4);
            const float rinv = 1.f / sum;
            for (int m = q; m < N_ANT; m += 8) Ss[t * SP + m] *= rinv;
        }
        __syncthreads();
        // ---- O[:, c0:c0+32] = P @ V[:, c0:c0+32]   (M=64, N=32, K=64) ----
        {
            const int nt = wrp >> 2;             // 1 n8-tile per warp
            float od[4] = {0.f, 0.f, 0.f, 0.f};
#pragma unroll
            for (int ks = 0; ks < 8; ks++) {
                const int kk = ks * 8;
                const unsigned a0 = cvt_tf32(Ss[r0 * SP + kk + tg]);
                const unsigned a1 = cvt_tf32(Ss[r1 * SP + kk + tg]);
                const unsigned a2 = cvt_tf32(Ss[r0 * SP + kk + tg + 4]);
                const unsigned a3 = cvt_tf32(Ss[r1 * SP + kk + tg + 4]);
                const unsigned b0 = cvt_tf32(V[(kk + tg) * AP + c0 + nt * 8 + g]);
                const unsigned b1 = cvt_tf32(V[(kk + tg + 4) * AP + c0 + nt * 8 + g]);
                mma8(od[0], od[1], od[2], od[3], a0, a1, a2, a3, b0, b1);
            }
            const int j = c0 + nt * 8 + 2 * tg;
            *reinterpret_cast<float2*>(O + r0 * AP + j) = make_float2(od[0], od[1]);
            *reinterpret_cast<float2*>(O + r1 * AP + j) = make_float2(od[2], od[3]);
        }
        __syncthreads();
    }
}

__global__ void __launch_bounds__(NTH, 1) drgn_kernel(
    const float* __restrict__ x, const int* __restrict__ mask,
    const float* __restrict__ hs,
    const float* __restrict__ enc_w, const float* __restrict__ enc_b,
    const float* __restrict__ q1_w, const float* __restrict__ q1_b,
    const float* __restrict__ k1_w, const float* __restrict__ k1_b,
    const float* __restrict__ v1_w, const float* __restrict__ v1_b,
    const float* __restrict__ o1_w, const float* __restrict__ o1_b,
    const float* __restrict__ q2_w, const float* __restrict__ q2_b,
    const float* __restrict__ k2_w, const float* __restrict__ k2_b,
    const float* __restrict__ v2_w, const float* __restrict__ v2_b,
    const float* __restrict__ o2_w, const float* __restrict__ o2_b,
    const float* __restrict__ w_ih, const float* __restrict__ w_hh,
    const float* __restrict__ b_ih, const float* __restrict__ b_hh,
    const float* __restrict__ lin_w, const float* __restrict__ lin_b,
    float* __restrict__ qs_out, float* __restrict__ h3_out, int act)
{
    extern __shared__ char smem_raw[];
    SmemLayout* s = reinterpret_cast<SmemLayout*>(smem_raw);
    const int tid = threadIdx.x;
    const int b   = blockIdx.x;

    // ---- load x tile and mask bitmap ----
    {
        const float* xb = x + (size_t)b * (N_ANT * 64);
        for (int idx = tid; idx < N_ANT * 64; idx += NTH)
            s->B0[(idx >> 6) * AP + (idx & 63)] = xb[idx];
        if (tid < N_ANT) {
            const int* mrow = mask + ((size_t)b * N_ANT + tid) * N_ANT;
            unsigned long long bits = 0ULL;
            for (int m = 0; m < N_ANT; m++)
                bits |= (unsigned long long)(mrow[m] != 0) << m;
            s->mb[tid] = bits;
        }
    }
    // (gemm_mma opens with __syncthreads -> orders the fills above)

    // ---- encoder: xe = relu(x @ enc_w^T) -> B1 ----
    {
        const float* W[1] = {enc_w}; const float* B[1] = {enc_b};
        float* Cc[1] = {s->B1};      const float* Tt[1] = {nullptr};
        gemm_mma<64, 1>(s->B0, W, B, Cc, Tt, nullptr, s->Ws, tid, EPI_RELU);
    }

    // ---- MHA layer 1: fused QKV from xe (B1) ----
    {
        const float* W[3] = {q1_w, k1_w, v1_w};
        const float* B[3] = {q1_b, k1_b, v1_b};
        float* Cc[3] = {s->B0, s->B2, s->B3};
        const float* Tt[3] = {nullptr, nullptr, nullptr};
        gemm_mma<128, 3>(s->B1, W, B, Cc, Tt, nullptr, s->Ws, tid, EPI_RELU);
    }
    attention_mma(s->B0, s->B2, s->B3, s->B1, s->Ss, s->mb, tid);
    {
        const float* W[1] = {o1_w}; const float* B[1] = {o1_b};
        float* Cc[1] = {s->B0};     const float* Tt[1] = {nullptr};
        gemm_mma<128, 1>(s->B1, W, B, Cc, Tt, nullptr, s->Ws, tid, EPI_RELU);  // h1 -> B0
    }

    // ---- MHA layer 2: fused QKV from h1 (B0) ----
    {
        const float* W[3] = {q2_w, k2_w, v2_w};
        const float* B[3] = {q2_b, k2_b, v2_b};
        float* Cc[3] = {s->B1, s->B2, s->B3};
        const float* Tt[3] = {nullptr, nullptr, nullptr};
        gemm_mma<128, 3>(s->B0, W, B, Cc, Tt, nullptr, s->Ws, tid, EPI_RELU);
    }
    attention_mma(s->B1, s->B2, s->B3, s->B0, s->Ss, s->mb, tid);
    {
        const float* W[1] = {o2_w}; const float* B[1] = {o2_b};
        float* Cc[1] = {s->B1};     const float* Tt[1] = {nullptr};
        gemm_mma<128, 1>(s->B0, W, B, Cc, Tt, nullptr, s->Ws, tid, EPI_RELU);  // h2 -> B1
    }

    // ---- load previous hidden state -> B2 ----
    {
        const float* hb = hs + (size_t)b * (N_ANT * HID);
        for (int idx = tid; idx < N_ANT * HID; idx += NTH)
            s->B2[(idx >> 7) * AP + (idx & 127)] = hb[idx];
    }

    // ---- GRU cell: h2 (B1), h (B2) ----
    {   // i_r -> B0, i_z -> B3  (fused, plain)
        const float* W[2] = {w_ih, w_ih + 128 * HID};
        const float* B[2] = {b_ih, b_ih + 128};
        float* Cc[2] = {s->B0, s->B3};
        const float* Tt[2] = {nullptr, nullptr};
        gemm_mma<128, 2>(s->B1, W, B, Cc, Tt, nullptr, s->Ws, tid, EPI_PLAIN);
    }
    {   // r = sig(i_r + h_r) -> B0 ; z = sig(i_z + h_z) -> B3  (fused)
        const float* W[2] = {w_hh, w_hh + 128 * HID};
        const float* B[2] = {b_hh, b_hh + 128};
        float* Cc[2] = {s->B0, s->B3};
        const float* Tt[2] = {s->B0, s->B3};
        gemm_mma<128, 2>(s->B2, W, B, Cc, Tt, nullptr, s->Ws, tid, EPI_SIGADD);
    }
    {   // i_n -> B1 (in place over h2; safe: sync precedes epilogue writes)
        const float* W[1] = {w_ih + 256 * HID}; const float* B[1] = {b_ih + 256};
        float* Cc[1] = {s->B1}; const float* Tt[1] = {nullptr};
        gemm_mma<128, 1>(s->B1, W, B, Cc, Tt, nullptr, s->Ws, tid, EPI_PLAIN);
    }
    {   // n = tanh(i_n + r * h_n) -> B1
        const float* W[1] = {w_hh + 256 * HID}; const float* B[1] = {b_hh + 256};
        float* Cc[1] = {s->B1}; const float* Tt[1] = {s->B1};
        gemm_mma<128, 1>(s->B2, W, B, Cc, Tt, s->B0, s->Ws, tid, EPI_TANHN);
    }

    // ---- h3 = (1-z)*n + z*h ; write h3 to gmem and keep in B1 ----
    {
        float* h3b = h3_out + (size_t)b * (N_ANT * HID);
        for (int idx = tid; idx < N_ANT * HID; idx += NTH) {
            const int off = (idx >> 7) * AP + (idx & 127);
            const float z  = s->B3[off];
            const float h3 = (1.f - z) * s->B1[off] + z * s->B2[off];
            s->B1[off] = h3;
            h3b[idx]   = h3;
        }
    }
    __syncthreads();

    // ---- qs = h3 @ lin_w^T + lin_b (scalar FFMA; tiny) ----
    {
        float* qb = qs_out + (size_t)b * (N_ANT * act);
        for (int idx = tid; idx < N_ANT * act; idx += NTH) {
            const int t = idx / act;
            const int a = idx - t * act;
            const float* wr = lin_w + a * HID;
            const float* hr = s->B1 + t * AP;
            float sacc = lin_b[a];
#pragma unroll 8
            for (int k = 0; k < HID; k += 4) {
                const float4 h4 = *reinterpret_cast<const float4*>(hr + k);
                const float4 w4 = *reinterpret_cast<const float4*>(wr + k);
                sacc = fmaf(h4.x, w4.x, sacc);
                sacc = fmaf(h4.y, w4.y, sacc);
                sacc = fmaf(h4.z, w4.z, sacc);
                sacc = fmaf(h4.w, w4.w, sacc);
            }
            qb[idx] = sacc;
        }
    }
}

extern "C" void kernel_launch(void* const* d_in, const int* in_sizes, int n_in,
                              void* d_out, int out_size)
{
    const float* x     = (const float*)d_in[0];
    const int*   mask  = (const int*)  d_in[1];
    const float* hs    = (const float*)d_in[2];
    const float* enc_w = (const float*)d_in[3];
    const float* enc_b = (const float*)d_in[4];
    const float* q1_w  = (const float*)d_in[5];
    const float* q1_b  = (const float*)d_in[6];
    const float* k1_w  = (const float*)d_in[7];
    const float* k1_b  = (const float*)d_in[8];
    const float* v1_w  = (const float*)d_in[9];
    const float* v1_b  = (const float*)d_in[10];
    const float* o1_w  = (const float*)d_in[11];
    const float* o1_b  = (const float*)d_in[12];
    const float* q2_w  = (const float*)d_in[13];
    const float* q2_b  = (const float*)d_in[14];
    const float* k2_w  = (const float*)d_in[15];
    const float* k2_b  = (const float*)d_in[16];
    const float* v2_w  = (const float*)d_in[17];
    const float* v2_b  = (const float*)d_in[18];
    const float* o2_w  = (const float*)d_in[19];
    const float* o2_b  = (const float*)d_in[20];
    const float* w_ih  = (const float*)d_in[21];
    const float* w_hh  = (const float*)d_in[22];
    const float* b_ih  = (const float*)d_in[23];
    const float* b_hh  = (const float*)d_in[24];
    const float* lin_w = (const float*)d_in[25];
    const float* lin_b = (const float*)d_in[26];

    const int bs  = in_sizes[0] / (N_ANT * 64);
    const int act = in_sizes[25] / HID;  // 20

    float* qs = (float*)d_out;
    float* h3 = qs + (size_t)bs * N_ANT * act;

    const int smem_bytes = (int)sizeof(SmemLayout);
    cudaFuncSetAttribute(drgn_kernel, cudaFuncAttributeMaxDynamicSharedMemorySize, smem_bytes);

    drgn_kernel<<<bs, NTH, smem_bytes>>>(
        x, mask, hs, enc_w, enc_b,
        q1_w, q1_b, k1_w, k1_b, v1_w, v1_b, o1_w, o1_b,
        q2_w, q2_b, k2_w, k2_b, v2_w, v2_b, o2_w, o2_b,
        w_ih, w_hh, b_ih, b_hh, lin_w, lin_b,
        qs, h3, act);
}